// round 5
// baseline (speedup 1.0000x reference)
#include <cuda_runtime.h>
#include <cuda_fp16.h>
#include <math.h>

#define ATTN_OFF 262144          // B*1024 head elems, then attn [B,T,T]

// ------------------- device globals (no allocation allowed) -------------------
__device__ __half g_UHh[33554432];         // [B*T, M] fp16  (67 MB)
__device__ __half g_Hh [33554432];         // fp16 copy of H (67 MB)
__device__ float  g_WdT[1024 * 512];       // W_d^T : [k=1024][col=512]
__device__ float  g_UdT[512 * 512];        // U_d^T : [m=512][n=512]
__device__ float  g_WT [1024 * 2048];      // [W_ih^T ; W_hh^T] : [k=1024][g=2048]
__device__ float  g_d  [131072];
__device__ float  g_s  [131072];
__device__ float  g_ct [131072];
__device__ float  g_wqp[4 * 131072];       // 4 k-quarter partials of wq
__device__ float  g_part[2 * 524288];      // 2 k-half partials of gates
__device__ float  g_e  [65536];            // e scores [B,T]

__device__ unsigned g_bar_count = 0;
__device__ unsigned g_bar_gen   = 0;
__device__ unsigned g_ctr[64];             // rotating work-steal counters

// ------------------- helpers -------------------
__device__ __forceinline__ float tanh_fast(float x) {
    float y;
    asm("tanh.approx.f32 %0, %1;" : "=f"(y) : "f"(x));
    return y;
}
__device__ __forceinline__ unsigned long long pack2(float x) {
    unsigned long long r;
    asm("mov.b64 %0, {%1, %1};" : "=l"(r) : "f"(x));
    return r;
}
__device__ __forceinline__ void fma2(unsigned long long& d,
                                     unsigned long long a, unsigned long long b) {
    asm("fma.rn.f32x2 %0, %1, %2, %0;" : "+l"(d) : "l"(a), "l"(b));
}
__device__ __forceinline__ float2 unpack2(unsigned long long a) {
    float2 f;
    asm("mov.b64 {%0, %1}, %2;" : "=f"(f.x), "=f"(f.y) : "l"(a));
    return f;
}

// sense-reversing grid barrier; releaser also zeroes a future steal slot
__device__ __forceinline__ void gsync(int G, int reset_slot) {
    __syncthreads();
    if (threadIdx.x == 0) {
        volatile unsigned* genp = (volatile unsigned*)&g_bar_gen;
        unsigned gen = *genp;
        __threadfence();
        if (atomicAdd(&g_bar_count, 1u) == (unsigned)(G - 1)) {
            g_bar_count = 0;
            g_ctr[reset_slot] = 0;
            __threadfence();
            *genp = gen + 1;
        } else {
            while (*genp == gen) { }
            __threadfence();
        }
    }
    __syncthreads();
}

// ------------------- the single persistent kernel -------------------
__global__ void __launch_bounds__(256, 3)
k_decoder(const float* __restrict__ H,  const float* __restrict__ d0,
          const float* __restrict__ s0, const float* __restrict__ W_d,
          const float* __restrict__ U_d, const float* __restrict__ v_d,
          const float* __restrict__ W_ih, const float* __restrict__ W_hh,
          const float* __restrict__ b_ih, const float* __restrict__ b_hh,
          float* __restrict__ out, int G) {
    __shared__ __align__(16) float sm[10240];   // 40 KB, reused per phase
    __shared__ int s_tile;

    const int tid = threadIdx.x;
    const int gtid = blockIdx.x * 256 + tid;
    const int nthr = G * 256;
    const int w = tid >> 5, lane = tid & 31;
    int pc = 0;

    // ---------------- preamble: transposes, init, fp16 H copy ----------------
    for (int i = gtid; i < 64; i += nthr) g_ctr[i] = 0;
    for (int i = gtid; i < 524288; i += nthr) {          // W_d -> WdT[k][col]
        int n = i >> 10, j = i & 1023;
        g_WdT[j * 512 + n] = W_d[i];
    }
    for (int i = gtid; i < 262144; i += nthr) {          // U_d -> UdT[m][n]
        int n = i >> 9, m = i & 511;
        g_UdT[m * 512 + n] = U_d[i];
    }
    for (int i = gtid; i < 1048576; i += nthr) {         // W_ih/W_hh -> WT[k][g]
        int gcol = i >> 9, m = i & 511;
        g_WT[(size_t)m * 2048 + gcol] = W_ih[i];
        g_WT[(size_t)(512 + m) * 2048 + gcol] = W_hh[i];
    }
    for (int i = gtid; i < 131072; i += nthr) {
        g_d[i] = d0[i];
        g_s[i] = s0[i];
    }
    for (int i = gtid; i < 8388608; i += nthr) {         // H fp16 copy (float4-wide)
        float4 h4 = *(const float4*)&H[(size_t)i * 4];
        __half2 lo = __floats2half2_rn(h4.x, h4.y);
        __half2 hi = __floats2half2_rn(h4.z, h4.w);
        *(__half2*)&g_Hh[(size_t)i * 4]     = lo;
        *(__half2*)&g_Hh[(size_t)i * 4 + 2] = hi;
    }
    gsync(G, 31);

    // ---------------- phase U: UH = H @ UdT (fp16 out), 8192 tiles ----------------
    {
        const int slot = pc & 63;
        for (;;) {
            __syncthreads();
            if (tid == 0) s_tile = atomicAdd(&g_ctr[slot], 1u);
            __syncthreads();
            const int tile = s_tile;
            if (tile >= 8192) break;
            const int i0 = tile * 8;
            for (int idx = tid; idx < 4096; idx += 256) {
                int r = idx >> 9, m = idx & 511;
                sm[m * 12 + r] = H[(size_t)(i0 + r) * 512 + m];
            }
            __syncthreads();

            const int c0 = 2 * tid;
            unsigned long long acc0[4] = {0, 0, 0, 0};
            unsigned long long acc1[4] = {0, 0, 0, 0};
#pragma unroll 4
            for (int m = 0; m < 512; m++) {
                float2 wv = *(const float2*)&g_UdT[m * 512 + c0];
                unsigned long long w0 = pack2(wv.x), w1 = pack2(wv.y);
                const float* hr = &sm[m * 12];
                ulonglong2 h01 = *(const ulonglong2*)&hr[0];
                ulonglong2 h23 = *(const ulonglong2*)&hr[4];
                fma2(acc0[0], w0, h01.x); fma2(acc1[0], w1, h01.x);
                fma2(acc0[1], w0, h01.y); fma2(acc1[1], w1, h01.y);
                fma2(acc0[2], w0, h23.x); fma2(acc1[2], w1, h23.x);
                fma2(acc0[3], w0, h23.y); fma2(acc1[3], w1, h23.y);
            }
#pragma unroll
            for (int rp = 0; rp < 4; rp++) {
                float2 a0 = unpack2(acc0[rp]);
                float2 a1 = unpack2(acc1[rp]);
                *(__half2*)&g_UHh[(size_t)(i0 + 2 * rp) * 512 + c0]     = __floats2half2_rn(a0.x, a1.x);
                *(__half2*)&g_UHh[(size_t)(i0 + 2 * rp + 1) * 512 + c0] = __floats2half2_rn(a0.y, a1.y);
            }
        }
        gsync(G, (pc + 32) & 63); pc++;
    }

    // ---------------- main scan: 256 steps ----------------
    for (int step = 0; step < 256; ++step) {
        // ---- P1: wq partials. 256 tiles = bg(32 of 8b) x cs(2) x kq(4) ----
        {
            const int slot = pc & 63;
            for (;;) {
                __syncthreads();
                if (tid == 0) s_tile = atomicAdd(&g_ctr[slot], 1u);
                __syncthreads();
                const int tile = s_tile;
                if (tile >= 256) break;
                const int bg = tile >> 3, cs = (tile >> 2) & 1, kq = tile & 3;
                const int b0 = bg * 8;
                const int col = cs * 256 + tid;
                const float* qsrc = (kq < 2) ? g_d : g_s;
                const int koff = (kq & 1) * 256;
                for (int idx = tid; idx < 2048; idx += 256) {
                    int r = idx >> 8, kk = idx & 255;
                    sm[kk * 12 + r] = qsrc[(b0 + r) * 512 + koff + kk];
                }
                __syncthreads();

                unsigned long long acc[4] = {0, 0, 0, 0};
                const float* wcol = &g_WdT[(kq * 256) * 512 + col];
#pragma unroll 4
                for (int kk = 0; kk < 256; kk++) {
                    unsigned long long w2 = pack2(wcol[kk * 512]);
                    const float* qr = &sm[kk * 12];
                    ulonglong2 q01 = *(const ulonglong2*)&qr[0];
                    ulonglong2 q23 = *(const ulonglong2*)&qr[4];
                    fma2(acc[0], w2, q01.x);
                    fma2(acc[1], w2, q01.y);
                    fma2(acc[2], w2, q23.x);
                    fma2(acc[3], w2, q23.y);
                }
                float* dst = &g_wqp[kq * 131072];
#pragma unroll
                for (int rp = 0; rp < 4; rp++) {
                    float2 a = unpack2(acc[rp]);
                    dst[(b0 + 2 * rp) * 512 + col] = a.x;
                    dst[(b0 + 2 * rp + 1) * 512 + col] = a.y;
                }
            }
            gsync(G, (pc + 32) & 63); pc++;
        }

        // ---- P2a: e scores. 1024 tiles = (b, t-quarter of 64) ----
        {
            const int slot = pc & 63;
            float* wqs = sm;
            float* vs  = sm + 512;
            for (;;) {
                __syncthreads();
                if (tid == 0) s_tile = atomicAdd(&g_ctr[slot], 1u);
                __syncthreads();
                const int tile = s_tile;
                if (tile >= 1024) break;
                const int b = tile >> 2, tq = tile & 3;
                for (int i = tid; i < 512; i += 256) {
                    wqs[i] = ((g_wqp[b * 512 + i] + g_wqp[131072 + b * 512 + i])
                              + g_wqp[262144 + b * 512 + i]) + g_wqp[393216 + b * 512 + i];
                    vs[i] = v_d[i];
                }
                __syncthreads();

                const int t0 = tq * 64 + w * 8;
                const __half* p = g_UHh + ((size_t)b * 256 + t0) * 512 + lane * 8;
                uint4 a0 = *(const uint4*)p;
                uint4 a1 = *(const uint4*)(p + 256);
#pragma unroll
                for (int j = 0; j < 8; j++) {
                    uint4 n0, n1;
                    if (j < 7) {
                        n0 = *(const uint4*)(p + 512);
                        n1 = *(const uint4*)(p + 768);
                    }
                    float acc = 0.f;
                    {
                        const int m = lane * 8;
                        float2 f0 = __half22float2(*(__half2*)&a0.x);
                        float2 f1 = __half22float2(*(__half2*)&a0.y);
                        float2 f2 = __half22float2(*(__half2*)&a0.z);
                        float2 f3 = __half22float2(*(__half2*)&a0.w);
                        float4 q0 = *(const float4*)&wqs[m];
                        float4 q1 = *(const float4*)&wqs[m + 4];
                        float4 v0 = *(const float4*)&vs[m];
                        float4 v1 = *(const float4*)&vs[m + 4];
                        acc += v0.x * tanh_fast(f0.x + q0.x);
                        acc += v0.y * tanh_fast(f0.y + q0.y);
                        acc += v0.z * tanh_fast(f1.x + q0.z);
                        acc += v0.w * tanh_fast(f1.y + q0.w);
                        acc += v1.x * tanh_fast(f2.x + q1.x);
                        acc += v1.y * tanh_fast(f2.y + q1.y);
                        acc += v1.z * tanh_fast(f3.x + q1.z);
                        acc += v1.w * tanh_fast(f3.y + q1.w);
                    }
                    {
                        const int m = 256 + lane * 8;
                        float2 f0 = __half22float2(*(__half2*)&a1.x);
                        float2 f1 = __half22float2(*(__half2*)&a1.y);
                        float2 f2 = __half22float2(*(__half2*)&a1.z);
                        float2 f3 = __half22float2(*(__half2*)&a1.w);
                        float4 q0 = *(const float4*)&wqs[m];
                        float4 q1 = *(const float4*)&wqs[m + 4];
                        float4 v0 = *(const float4*)&vs[m];
                        float4 v1 = *(const float4*)&vs[m + 4];
                        acc += v0.x * tanh_fast(f0.x + q0.x);
                        acc += v0.y * tanh_fast(f0.y + q0.y);
                        acc += v0.z * tanh_fast(f1.x + q0.z);
                        acc += v0.w * tanh_fast(f1.y + q0.w);
                        acc += v1.x * tanh_fast(f2.x + q1.x);
                        acc += v1.y * tanh_fast(f2.y + q1.y);
                        acc += v1.z * tanh_fast(f3.x + q1.z);
                        acc += v1.w * tanh_fast(f3.y + q1.w);
                    }
#pragma unroll
                    for (int off = 16; off; off >>= 1)
                        acc += __shfl_xor_sync(0xffffffffu, acc, off);
                    if (lane == 0) g_e[b * 256 + t0 + j] = acc;
                    a0 = n0; a1 = n1; p += 512;
                }
            }
            gsync(G, (pc + 32) & 63); pc++;
        }

        // ---- P2b: softmax + attn + ct. 1024 tiles = (b, col-quarter of 128) ----
        {
            const int slot = pc & 63;
            float* beta = sm;           // 256
            float* red8 = sm + 256;     // 8
            float* red2 = sm + 512;     // 16 * 132
            for (;;) {
                __syncthreads();
                if (tid == 0) s_tile = atomicAdd(&g_ctr[slot], 1u);
                __syncthreads();
                const int tile = s_tile;
                if (tile >= 1024) break;
                const int b = tile >> 2, cq = tile & 3;

                float ev = g_e[b * 256 + tid];
                float mv = ev;
#pragma unroll
                for (int off = 16; off; off >>= 1)
                    mv = fmaxf(mv, __shfl_xor_sync(0xffffffffu, mv, off));
                if (lane == 0) red8[w] = mv;
                __syncthreads();
                float bm = red8[0];
#pragma unroll
                for (int i = 1; i < 8; i++) bm = fmaxf(bm, red8[i]);
                float ex = __expf(ev - bm);
                float sv = ex;
#pragma unroll
                for (int off = 16; off; off >>= 1)
                    sv += __shfl_xor_sync(0xffffffffu, sv, off);
                __syncthreads();
                if (lane == 0) red8[w] = sv;
                __syncthreads();
                float bs = 0.f;
#pragma unroll
                for (int i = 0; i < 8; i++) bs += red8[i];
                float bt = ex / bs;
                beta[tid] = bt;
                if (cq == 0)
                    out[(size_t)ATTN_OFF + (size_t)b * 65536 + (size_t)step * 256 + tid] = bt;
                __syncthreads();

                // ct: thread (g=tid>>4, c=tid&15) -> 8 cols, 16 t's
                const int c = tid & 15, gg = tid >> 4;
                const __half* hp = g_Hh + (size_t)b * 131072
                                   + (size_t)(gg * 16) * 512 + cq * 128 + c * 8;
                float f0 = 0.f, f1 = 0.f, f2 = 0.f, f3 = 0.f;
                float f4 = 0.f, f5 = 0.f, f6 = 0.f, f7 = 0.f;
#pragma unroll 4
                for (int i = 0; i < 16; i++) {
                    uint4 hv = *(const uint4*)(hp + (size_t)i * 512);
                    float bv = beta[gg * 16 + i];
                    float2 h0 = __half22float2(*(__half2*)&hv.x);
                    float2 h1 = __half22float2(*(__half2*)&hv.y);
                    float2 h2 = __half22float2(*(__half2*)&hv.z);
                    float2 h3 = __half22float2(*(__half2*)&hv.w);
                    f0 += bv * h0.x; f1 += bv * h0.y;
                    f2 += bv * h1.x; f3 += bv * h1.y;
                    f4 += bv * h2.x; f5 += bv * h2.y;
                    f6 += bv * h3.x; f7 += bv * h3.y;
                }
                float4 w0 = make_float4(f0, f1, f2, f3);
                float4 w1 = make_float4(f4, f5, f6, f7);
                *(float4*)&red2[gg * 132 + c * 8]     = w0;
                *(float4*)&red2[gg * 132 + c * 8 + 4] = w1;
                __syncthreads();
                if (tid < 128) {
                    float s = 0.f;
#pragma unroll
                    for (int g2 = 0; g2 < 16; g2++) s += red2[g2 * 132 + tid];
                    g_ct[b * 512 + cq * 128 + tid] = s;
                }
            }
            gsync(G, (pc + 32) & 63); pc++;
        }

        // ---- P3a: gates partials. 256 tiles = bg(16 of 16b) x cs(8) x kh(2) ----
        {
            const int slot = pc & 63;
            for (;;) {
                __syncthreads();
                if (tid == 0) s_tile = atomicAdd(&g_ctr[slot], 1u);
                __syncthreads();
                const int tile = s_tile;
                if (tile >= 256) break;
                const int bg = tile >> 4, cs = (tile >> 1) & 7, kh = tile & 1;
                const int b0 = bg * 16;
                const int col = cs * 256 + tid;
                const float* qsrc = kh ? g_d : g_ct;
                for (int idx = tid; idx < 8192; idx += 256) {
                    int r = idx >> 9, kk = idx & 511;
                    sm[kk * 20 + r] = qsrc[(b0 + r) * 512 + kk];
                }
                __syncthreads();

                unsigned long long acc[8] = {0, 0, 0, 0, 0, 0, 0, 0};
                const float* wcol = &g_WT[(size_t)(kh * 512) * 2048 + col];
#pragma unroll 2
                for (int kk = 0; kk < 512; kk++) {
                    unsigned long long w2 = pack2(wcol[(size_t)kk * 2048]);
                    const float* qr = &sm[kk * 20];
                    ulonglong2 q01 = *(const ulonglong2*)&qr[0];
                    ulonglong2 q23 = *(const ulonglong2*)&qr[4];
                    ulonglong2 q45 = *(const ulonglong2*)&qr[8];
                    ulonglong2 q67 = *(const ulonglong2*)&qr[12];
                    fma2(acc[0], w2, q01.x); fma2(acc[1], w2, q01.y);
                    fma2(acc[2], w2, q23.x); fma2(acc[3], w2, q23.y);
                    fma2(acc[4], w2, q45.x); fma2(acc[5], w2, q45.y);
                    fma2(acc[6], w2, q67.x); fma2(acc[7], w2, q67.y);
                }
                float* dst = &g_part[kh * 524288];
#pragma unroll
                for (int rp = 0; rp < 8; rp++) {
                    float2 a = unpack2(acc[rp]);
                    dst[(b0 + 2 * rp) * 2048 + col] = a.x;
                    dst[(b0 + 2 * rp + 1) * 2048 + col] = a.y;
                }
            }
            gsync(G, (pc + 32) & 63); pc++;
        }

        // ---- P3b: LSTM update (elementwise) ----
        for (int idx = gtid; idx < 131072; idx += nthr) {
            const int b = idx >> 9, p = idx & 511;
            const float* p0 = &g_part[b * 2048];
            const float* p1 = &g_part[524288 + b * 2048];
            float gi = (p0[p] + p1[p]) + (b_ih[p] + b_hh[p]);
            float gf = (p0[512 + p] + p1[512 + p]) + (b_ih[512 + p] + b_hh[512 + p]);
            float gg = (p0[1024 + p] + p1[1024 + p]) + (b_ih[1024 + p] + b_hh[1024 + p]);
            float go = (p0[1536 + p] + p1[1536 + p]) + (b_ih[1536 + p] + b_hh[1536 + p]);
            float si = 1.f / (1.f + __expf(-gi));
            float sf = 1.f / (1.f + __expf(-gf));
            float so = 1.f / (1.f + __expf(-go));
            float s_new = sf * g_s[idx] + si * tanh_fast(gg);
            g_s[idx] = s_new;
            g_d[idx] = so * tanh_fast(s_new);
        }
        gsync(G, (pc + 32) & 63); pc++;
    }

    // ---------------- epilogue: out head = [d_final ; ct_last] ----------------
    for (int i = gtid; i < 262144; i += nthr) {
        int b = i >> 10, j = i & 1023;
        out[i] = (j < 512) ? g_d[b * 512 + j] : g_ct[b * 512 + (j - 512)];
    }
}

// ------------------- launch -------------------
extern "C" void kernel_launch(void* const* d_in, const int* in_sizes, int n_in,
                              void* d_out, int out_size) {
    (void)in_sizes; (void)n_in; (void)out_size;
    const float* H    = (const float*)d_in[0];
    const float* d0   = (const float*)d_in[1];
    const float* s0   = (const float*)d_in[2];
    const float* W_d  = (const float*)d_in[3];
    const float* U_d  = (const float*)d_in[4];
    const float* v_d  = (const float*)d_in[5];
    const float* W_ih = (const float*)d_in[6];
    const float* W_hh = (const float*)d_in[7];
    const float* b_ih = (const float*)d_in[8];
    const float* b_hh = (const float*)d_in[9];
    float* out = (float*)d_out;

    int dev = 0, sms = 148;
    cudaGetDevice(&dev);
    cudaDeviceGetAttribute(&sms, cudaDevAttrMultiProcessorCount, dev);
    int occ = 3;
    cudaOccupancyMaxActiveBlocksPerMultiprocessor(&occ, k_decoder, 256, 0);
    if (occ < 1) occ = 1;
    if (occ > 3) occ = 3;
    int G = sms * occ;

    k_decoder<<<G, 256>>>(H, d0, s0, W_d, U_d, v_d, W_ih, W_hh, b_ih, b_hh, out, G);
}

// round 6
// speedup vs baseline: 1.0296x; 1.0296x over previous
#include <cuda_runtime.h>
#include <cuda_fp16.h>
#include <math.h>

#define ATTN_OFF 262144          // B*1024 head elems, then attn [B,T,T]
#define GBLK 128                 // grid: 128 blocks x 512 threads, 1/SM

// ------------------- device globals (no allocation allowed) -------------------
__device__ __half g_UHh[33554432];         // [B*T, M] fp16  (67 MB)
__device__ __half g_Hh [33554432];         // fp16 copy of H (67 MB)
__device__ float  g_WdT[1024 * 512];       // W_d^T : [k=1024][col=512]
__device__ float  g_UdT[512 * 512];        // U_d^T : [m=512][n=512]
__device__ float  g_WT [1024 * 2048];      // [W_ih^T ; W_hh^T] : [k=1024][g=2048]
__device__ float  g_bias[2048];            // b_ih + b_hh
__device__ float  g_d  [131072];
__device__ float  g_s  [131072];
__device__ float  g_ct [131072];
__device__ float  g_wq [131072];
__device__ float  g_gates[524288];         // raw gates [B, 4P]

__device__ unsigned g_bar_count = 0;
__device__ unsigned g_bar_gen   = 0;

// ------------------- helpers -------------------
__device__ __forceinline__ float tanh_fast(float x) {
    float y;
    asm("tanh.approx.f32 %0, %1;" : "=f"(y) : "f"(x));
    return y;
}
__device__ __forceinline__ float sigmoid_fast(float x) {
    return 1.f / (1.f + __expf(-x));
}
__device__ __forceinline__ unsigned long long pack2(float x) {
    unsigned long long r;
    asm("mov.b64 %0, {%1, %1};" : "=l"(r) : "f"(x));
    return r;
}
__device__ __forceinline__ void fma2(unsigned long long& d,
                                     unsigned long long a, unsigned long long b) {
    asm("fma.rn.f32x2 %0, %1, %2, %0;" : "+l"(d) : "l"(a), "l"(b));
}
__device__ __forceinline__ float2 unpack2(unsigned long long a) {
    float2 f;
    asm("mov.b64 {%0, %1}, %2;" : "=f"(f.x), "=f"(f.y) : "l"(a));
    return f;
}

// sense-reversing grid barrier (leader polls, rest wait at bar.sync)
__device__ __forceinline__ void gsync() {
    __syncthreads();
    if (threadIdx.x == 0) {
        volatile unsigned* genp = (volatile unsigned*)&g_bar_gen;
        unsigned gen = *genp;
        __threadfence();
        if (atomicAdd(&g_bar_count, 1u) == (unsigned)(GBLK - 1)) {
            g_bar_count = 0;
            __threadfence();
            *genp = gen + 1;
        } else {
            while (*genp == gen) { }
            __threadfence();
        }
    }
    __syncthreads();
}

// ------------------- the single persistent kernel -------------------
__global__ void __launch_bounds__(512, 1)
k_decoder(const float* __restrict__ H,  const float* __restrict__ d0,
          const float* __restrict__ s0, const float* __restrict__ W_d,
          const float* __restrict__ U_d, const float* __restrict__ v_d,
          const float* __restrict__ W_ih, const float* __restrict__ W_hh,
          const float* __restrict__ b_ih, const float* __restrict__ b_hh,
          float* __restrict__ out) {
    __shared__ __align__(16) float sm[12288];     // 48 KB, reused per phase

    const int tid  = threadIdx.x;
    const int bid  = blockIdx.x;
    const int gtid = bid * 512 + tid;
    const int nthr = GBLK * 512;                  // 65536
    const int w = tid >> 5, lane = tid & 31;

    // ---------------- preamble: transposes, bias, fp16 H copy ----------------
    for (int i = gtid; i < 524288; i += nthr) {            // W_d -> WdT[k][col]
        int n = i >> 10, j = i & 1023;
        g_WdT[j * 512 + n] = W_d[i];
    }
    for (int i = gtid; i < 262144; i += nthr) {            // U_d -> UdT[m][n]
        int n = i >> 9, m = i & 511;
        g_UdT[m * 512 + n] = U_d[i];
    }
    for (int i = gtid; i < 1048576; i += nthr) {           // W_ih/W_hh -> WT[k][g]
        int gcol = i >> 9, m = i & 511;
        g_WT[(size_t)m * 2048 + gcol] = W_ih[i];
        g_WT[(size_t)(512 + m) * 2048 + gcol] = W_hh[i];
    }
    for (int i = gtid; i < 2048; i += nthr)
        g_bias[i] = b_ih[i] + b_hh[i];
    for (int i = gtid; i < 8388608; i += nthr) {           // H -> fp16 (float4-wide)
        float4 h4 = *(const float4*)&H[(size_t)i * 4];
        *(__half2*)&g_Hh[(size_t)i * 4]     = __floats2half2_rn(h4.x, h4.y);
        *(__half2*)&g_Hh[(size_t)i * 4 + 2] = __floats2half2_rn(h4.z, h4.w);
    }
    gsync();

    // ---------------- phase U: UH = H @ UdT (fp16 out). 64 tiles/block ----------------
    for (int it = 0; it < 64; it++) {
        const int i0 = (bid * 64 + it) * 8;                // 8 rows per tile
        __syncthreads();
        for (int idx = tid; idx < 4096; idx += 512) {      // sm[m*12 + r]
            int m = idx & 511, r = idx >> 9;
            sm[m * 12 + r] = H[(size_t)(i0 + r) * 512 + m];
        }
        __syncthreads();

        unsigned long long acc[4] = {0, 0, 0, 0};
        const float* wcol = &g_UdT[tid];
#pragma unroll 4
        for (int m = 0; m < 512; m++) {
            unsigned long long w2 = pack2(wcol[m * 512]);
            const float* qr = &sm[m * 12];
            ulonglong2 q01 = *(const ulonglong2*)&qr[0];
            ulonglong2 q23 = *(const ulonglong2*)&qr[4];
            fma2(acc[0], w2, q01.x); fma2(acc[1], w2, q01.y);
            fma2(acc[2], w2, q23.x); fma2(acc[3], w2, q23.y);
        }
#pragma unroll
        for (int rp = 0; rp < 4; rp++) {
            float2 a = unpack2(acc[rp]);
            g_UHh[(size_t)(i0 + 2 * rp) * 512 + tid]     = __float2half_rn(a.x);
            g_UHh[(size_t)(i0 + 2 * rp + 1) * 512 + tid] = __float2half_rn(a.y);
        }
    }
    gsync();

    // ---------------- main scan: 256 steps, 3 barriers each ----------------
    for (int step = 0; step < 256; ++step) {
        // ---- P1: LSTM (state for this step) + wq GEMM. tile = 2 batches, full cols/K ----
        {
            const int b0 = bid * 2;
            float dnew[2], snew[2];
            if (step == 0) {
#pragma unroll
                for (int r = 0; r < 2; r++) {
                    dnew[r] = d0[(b0 + r) * 512 + tid];
                    snew[r] = s0[(b0 + r) * 512 + tid];
                }
            } else {
#pragma unroll
                for (int r = 0; r < 2; r++) {
                    const int b = b0 + r;
                    const float* gr = &g_gates[b * 2048];
                    float gi = gr[tid]         + g_bias[tid];
                    float gf = gr[512 + tid]   + g_bias[512 + tid];
                    float gg = gr[1024 + tid]  + g_bias[1024 + tid];
                    float go = gr[1536 + tid]  + g_bias[1536 + tid];
                    float s_old = g_s[b * 512 + tid];
                    float s_new = sigmoid_fast(gf) * s_old
                                + sigmoid_fast(gi) * tanh_fast(gg);
                    snew[r] = s_new;
                    dnew[r] = sigmoid_fast(go) * tanh_fast(s_new);
                }
            }
#pragma unroll
            for (int r = 0; r < 2; r++) {
                sm[tid * 2 + r]         = dnew[r];          // q[k<512]  = d
                sm[(512 + tid) * 2 + r] = snew[r];          // q[k>=512] = s
                g_d[(b0 + r) * 512 + tid] = dnew[r];
                g_s[(b0 + r) * 512 + tid] = snew[r];
            }
            __syncthreads();

            // wq[b0..b0+1, col=tid] over k=1024 (dual chains)
            unsigned long long acc0 = 0, acc1 = 0;
            const float* wcol = &g_WdT[tid];
#pragma unroll 8
            for (int k = 0; k < 1024; k += 2) {
                unsigned long long w0 = pack2(wcol[k * 512]);
                unsigned long long w1 = pack2(wcol[(k + 1) * 512]);
                fma2(acc0, w0, *(const unsigned long long*)&sm[k * 2]);
                fma2(acc1, w1, *(const unsigned long long*)&sm[(k + 1) * 2]);
            }
            float2 a0 = unpack2(acc0), a1 = unpack2(acc1);
            g_wq[b0 * 512 + tid]       = a0.x + a1.x;
            g_wq[(b0 + 1) * 512 + tid] = a0.y + a1.y;
        }
        gsync();

        // ---- P2 (fused): e -> softmax -> attn -> ct. block owns 2 batches ----
        {
            float* wqs  = sm;            // 512
            float* vs   = sm + 512;      // 512
            float* es   = sm + 1024;     // 256
            float* beta = sm + 1280;     // 256
            float* red8 = sm + 1536;     // 8
            float* red  = sm + 1600;     // 8 * 520
            for (int bi = 0; bi < 2; bi++) {
                const int b = bid * 2 + bi;
                __syncthreads();
                if (tid < 512) {                       // all threads
                    wqs[tid] = g_wq[b * 512 + tid];
                    vs[tid]  = v_d[tid];
                }
                __syncthreads();

                // e[t]: warp w owns t = w*16 .. w*16+15, double-buffered rows
                {
                    const int t0 = w * 16;
                    const __half* p = g_UHh + ((size_t)b * 256 + t0) * 512 + lane * 8;
                    uint4 a0 = *(const uint4*)p;
                    uint4 a1 = *(const uint4*)(p + 256);
#pragma unroll
                    for (int j = 0; j < 16; j++) {
                        uint4 n0, n1;
                        if (j < 15) {
                            n0 = *(const uint4*)(p + 512);
                            n1 = *(const uint4*)(p + 768);
                        }
                        float acc = 0.f;
#pragma unroll
                        for (int half_ix = 0; half_ix < 2; half_ix++) {
                            const uint4 u = half_ix ? a1 : a0;
                            const int m = half_ix * 256 + lane * 8;
                            float2 f0 = __half22float2(*(__half2*)&u.x);
                            float2 f1 = __half22float2(*(__half2*)&u.y);
                            float2 f2 = __half22float2(*(__half2*)&u.z);
                            float2 f3 = __half22float2(*(__half2*)&u.w);
                            float4 q0 = *(const float4*)&wqs[m];
                            float4 q1 = *(const float4*)&wqs[m + 4];
                            float4 v0 = *(const float4*)&vs[m];
                            float4 v1 = *(const float4*)&vs[m + 4];
                            acc += v0.x * tanh_fast(f0.x + q0.x);
                            acc += v0.y * tanh_fast(f0.y + q0.y);
                            acc += v0.z * tanh_fast(f1.x + q0.z);
                            acc += v0.w * tanh_fast(f1.y + q0.w);
                            acc += v1.x * tanh_fast(f2.x + q1.x);
                            acc += v1.y * tanh_fast(f2.y + q1.y);
                            acc += v1.z * tanh_fast(f3.x + q1.z);
                            acc += v1.w * tanh_fast(f3.y + q1.w);
                        }
#pragma unroll
                        for (int off = 16; off; off >>= 1)
                            acc += __shfl_xor_sync(0xffffffffu, acc, off);
                        if (lane == 0) es[t0 + j] = acc;
                        a0 = n0; a1 = n1; p += 512;
                    }
                }
                __syncthreads();

                // softmax over es[256] using threads 0..255
                if (tid < 256) {
                    float ev = es[tid];
                    float mv = ev;
#pragma unroll
                    for (int off = 16; off; off >>= 1)
                        mv = fmaxf(mv, __shfl_xor_sync(0xffffffffu, mv, off));
                    if (lane == 0) red8[w] = mv;
                }
                __syncthreads();
                if (tid < 256) {
                    float bm = red8[0];
#pragma unroll
                    for (int i = 1; i < 8; i++) bm = fmaxf(bm, red8[i]);
                    float ex = __expf(es[tid] - bm);
                    beta[tid] = ex;          // temp: unnormalized
                    float sv = ex;
#pragma unroll
                    for (int off = 16; off; off >>= 1)
                        sv += __shfl_xor_sync(0xffffffffu, sv, off);
                    if (lane == 0) es[w] = sv;   // reuse es[0..7] for sums
                }
                __syncthreads();
                if (tid < 256) {
                    float bs = 0.f;
#pragma unroll
                    for (int i = 0; i < 8; i++) bs += es[i];
                    float bt = beta[tid] / bs;
                    beta[tid] = bt;
                    out[(size_t)ATTN_OFF + (size_t)b * 65536
                        + (size_t)step * 256 + tid] = bt;
                }
                __syncthreads();

                // ct: thread (c = tid&63 -> 8 cols, g2 = tid>>6 -> 32 t's), 4 loads in flight
                {
                    const int c = tid & 63, g2 = tid >> 6;
                    const __half* hp = g_Hh + (size_t)b * 131072
                                       + (size_t)(g2 * 32) * 512 + c * 8;
                    float f[8] = {0.f, 0.f, 0.f, 0.f, 0.f, 0.f, 0.f, 0.f};
#pragma unroll
                    for (int i4 = 0; i4 < 8; i4++) {
                        uint4 hv0 = *(const uint4*)(hp);
                        uint4 hv1 = *(const uint4*)(hp + 512);
                        uint4 hv2 = *(const uint4*)(hp + 1024);
                        uint4 hv3 = *(const uint4*)(hp + 1536);
                        const float* bp = &beta[g2 * 32 + i4 * 4];
#pragma unroll
                        for (int u = 0; u < 4; u++) {
                            const uint4 hv = (u == 0) ? hv0 : (u == 1) ? hv1
                                             : (u == 2) ? hv2 : hv3;
                            float bv = bp[u];
                            float2 h0 = __half22float2(*(__half2*)&hv.x);
                            float2 h1 = __half22float2(*(__half2*)&hv.y);
                            float2 h2 = __half22float2(*(__half2*)&hv.z);
                            float2 h3 = __half22float2(*(__half2*)&hv.w);
                            f[0] += bv * h0.x; f[1] += bv * h0.y;
                            f[2] += bv * h1.x; f[3] += bv * h1.y;
                            f[4] += bv * h2.x; f[5] += bv * h2.y;
                            f[6] += bv * h3.x; f[7] += bv * h3.y;
                        }
                        hp += 2048;
                    }
                    *(float4*)&red[g2 * 520 + c * 8]     = make_float4(f[0], f[1], f[2], f[3]);
                    *(float4*)&red[g2 * 520 + c * 8 + 4] = make_float4(f[4], f[5], f[6], f[7]);
                }
                __syncthreads();
                {
                    float s = 0.f;
#pragma unroll
                    for (int g3 = 0; g3 < 8; g3++) s += red[g3 * 520 + tid];
                    g_ct[b * 512 + tid] = s;
                }
            }
        }
        gsync();

        // ---- P3: gates GEMM, full K=1024. tile = 8 batches x 512 cols ----
        {
            const int b0 = (bid >> 2) * 8;
            const int col = (bid & 3) * 512 + tid;
            for (int idx = tid; idx < 8192; idx += 512) {   // sm[k*12 + r]
                int k = idx & 1023, r = idx >> 10;
                float v = (k < 512) ? g_ct[(b0 + r) * 512 + k]
                                    : g_d[(b0 + r) * 512 + (k - 512)];
                sm[k * 12 + r] = v;
            }
            __syncthreads();

            unsigned long long acc[4] = {0, 0, 0, 0};
            const float* wcol = &g_WT[col];
#pragma unroll 4
            for (int k = 0; k < 1024; k++) {
                unsigned long long w2 = pack2(wcol[(size_t)k * 2048]);
                const float* qr = &sm[k * 12];
                ulonglong2 q01 = *(const ulonglong2*)&qr[0];
                ulonglong2 q23 = *(const ulonglong2*)&qr[4];
                fma2(acc[0], w2, q01.x); fma2(acc[1], w2, q01.y);
                fma2(acc[2], w2, q23.x); fma2(acc[3], w2, q23.y);
            }
#pragma unroll
            for (int rp = 0; rp < 4; rp++) {
                float2 a = unpack2(acc[rp]);
                g_gates[(b0 + 2 * rp) * 2048 + col]     = a.x;
                g_gates[(b0 + 2 * rp + 1) * 2048 + col] = a.y;
            }
            __syncthreads();
        }
        gsync();
    }

    // ---------------- epilogue: final LSTM -> out head [d_final ; ct_last] ----------------
    for (int idx = gtid; idx < 131072; idx += nthr) {
        const int b = idx >> 9, p = idx & 511;
        const float* gr = &g_gates[b * 2048];
        float gi = gr[p]        + g_bias[p];
        float gf = gr[512 + p]  + g_bias[512 + p];
        float gg = gr[1024 + p] + g_bias[1024 + p];
        float go = gr[1536 + p] + g_bias[1536 + p];
        float s_new = sigmoid_fast(gf) * g_s[idx] + sigmoid_fast(gi) * tanh_fast(gg);
        float d_new = sigmoid_fast(go) * tanh_fast(s_new);
        out[b * 1024 + p]       = d_new;
        out[b * 1024 + 512 + p] = g_ct[idx];
    }
}

// ------------------- launch -------------------
extern "C" void kernel_launch(void* const* d_in, const int* in_sizes, int n_in,
                              void* d_out, int out_size) {
    (void)in_sizes; (void)n_in; (void)out_size;
    const float* H    = (const float*)d_in[0];
    const float* d0   = (const float*)d_in[1];
    const float* s0   = (const float*)d_in[2];
    const float* W_d  = (const float*)d_in[3];
    const float* U_d  = (const float*)d_in[4];
    const float* v_d  = (const float*)d_in[5];
    const float* W_ih = (const float*)d_in[6];
    const float* W_hh = (const float*)d_in[7];
    const float* b_ih = (const float*)d_in[8];
    const float* b_hh = (const float*)d_in[9];
    float* out = (float*)d_out;

    k_decoder<<<GBLK, 512>>>(H, d0, s0, W_d, U_d, v_d, W_ih, W_hh, b_ih, b_hh, out);
}